// round 11
// baseline (speedup 1.0000x reference)
#include <cuda_runtime.h>
#include <math.h>
#include <stdint.h>

// Problem constants
#define Bb    8
#define Tt    4096
#define Cc    512
#define Hh    8
#define Dd    64
#define Ww    128
#define NROWS (Bb*Tt)          // 32768
#define NWIN  (Tt/Ww)          // 32

// Scratch (device globals: allocation-free rule)
__device__ float g_Q[(size_t)NROWS*Cc];
__device__ float g_K[(size_t)NROWS*Cc];
__device__ float g_V[(size_t)NROWS*Cc];
__device__ float g_O[(size_t)NROWS*Cc];   // attn output, tf32-rounded at write
__device__ float g_Wt[(size_t)4*Cc*Cc];   // tf32-converted weights [K][N]
__device__ float g_cos[Tt*32];
__device__ float g_sin[Tt*32];

// ---------------------------------------------------------------------------
// tf32 conversion (round-to-nearest-A).
// ---------------------------------------------------------------------------
__device__ __forceinline__ uint32_t f2tf32(float f) {
    uint32_t r;
    asm("cvt.rna.tf32.f32 %0, %1;" : "=r"(r) : "f"(f));
    return r;
}
__device__ __forceinline__ float f2tf32f(float f) {
    return __uint_as_float(f2tf32(f));
}

// ---------------------------------------------------------------------------
// Fused prep: RoPE tables (131072 items) + 4 weight tf32-cvts (4*65536 float4).
// One launch instead of five.
// ---------------------------------------------------------------------------
#define ROPE_N   (Tt*32)             // 131072
#define CVT_N4   (Cc*Cc/4)           // 65536
#define PREP_TOT (ROPE_N + 4*CVT_N4) // 393216

__global__ void prep_kernel(const float* __restrict__ W0,
                            const float* __restrict__ W1,
                            const float* __restrict__ W2,
                            const float* __restrict__ W3,
                            float* __restrict__ Wt) {
    int i = blockIdx.x * blockDim.x + threadIdx.x;
    if (i < ROPE_N) {
        int t = i >> 5, d = i & 31;
        float invf = (float)exp(-(double)d * (log(10000.0) / 32.0));
        float ang  = (float)t * invf;
        double s, c;
        sincos((double)ang, &s, &c);
        g_cos[i] = (float)c;
        g_sin[i] = (float)s;
    } else if (i < PREP_TOT) {
        int j = i - ROPE_N;
        int z = j >> 16;            // CVT_N4 == 65536
        int idx = j & 65535;
        const float* W = (z == 0) ? W0 : (z == 1) ? W1 : (z == 2) ? W2 : W3;
        float4 v = ((const float4*)W)[idx];
        uint4 o;
        o.x = f2tf32(v.x); o.y = f2tf32(v.y);
        o.z = f2tf32(v.z); o.w = f2tf32(v.w);
        ((uint4*)(Wt + (size_t)z * Cc * Cc))[idx] = o;
    }
}

// ---------------------------------------------------------------------------
// GEMM path A: tf32 mma.sync tensor body (unchanged from R10).
// BM=BN=128, BK=32, 256 threads, 3-stage cp.async pipeline.
// ---------------------------------------------------------------------------
#define ASZ_B   18432            // 128*36*4
#define BSZ_B   17408            // 32*136*4
#define STAGE_B 35840            // ASZ_B + BSZ_B
#define NPIPE   3
#define GSMEM   (NPIPE*STAGE_B)  // 107520

template <bool CVT_A>
__device__ __forceinline__ void gemm_body(
    const float* __restrict__ A, const float* __restrict__ Bw,
    float* __restrict__ C, int bm, int bcol)
{
    extern __shared__ char smem[];
    float* smf = (float*)smem;
    uint32_t sbase;
    asm("{ .reg .u64 t; cvta.to.shared.u64 t, %1; cvt.u32.u64 %0, t; }"
        : "=r"(sbase) : "l"(smem));

    int tid = threadIdx.x;
    int lane = tid & 31;
    int wid = tid >> 5;
    int warpM = wid & 3;
    int warpN = wid >> 2;
    int gr = lane >> 2;
    int gc = lane & 3;

    const float* Ag = A + (size_t)(bm * 128) * Cc;

    auto load_stage = [&](int s, int buf) {
        int k0 = s * 32;
        uint32_t ab = sbase + buf * STAGE_B;
        uint32_t bb = ab + ASZ_B;
        #pragma unroll
        for (int i = 0; i < 4; i++) {
            int idx = tid + i * 256;
            int r = idx >> 3, c4 = idx & 7;
            const float* src = Ag + (size_t)r * Cc + k0 + c4 * 4;
            uint32_t dst = ab + r * 144 + c4 * 16;
            asm volatile("cp.async.cg.shared.global [%0], [%1], 16;"
                         :: "r"(dst), "l"(src) : "memory");
        }
        #pragma unroll
        for (int i = 0; i < 4; i++) {
            int idx = tid + i * 256;
            int r = idx >> 5, c4 = idx & 31;
            const float* src = Bw + (size_t)(k0 + r) * Cc + bcol * 128 + c4 * 4;
            uint32_t dst = bb + r * 544 + c4 * 16;
            asm volatile("cp.async.cg.shared.global [%0], [%1], 16;"
                         :: "r"(dst), "l"(src) : "memory");
        }
        asm volatile("cp.async.commit_group;" ::: "memory");
    };

    float acc[2][8][4];
    #pragma unroll
    for (int mt = 0; mt < 2; mt++)
        #pragma unroll
        for (int nt = 0; nt < 8; nt++)
            #pragma unroll
            for (int j = 0; j < 4; j++) acc[mt][nt][j] = 0.f;

    load_stage(0, 0);
    load_stage(1, 1);

    int buf = 0;
    #pragma unroll 1
    for (int s = 0; s < 16; s++) {
        if (s + 2 < 16) {
            asm volatile("cp.async.wait_group 1;" ::: "memory");
        } else {
            asm volatile("cp.async.wait_group 0;" ::: "memory");
        }
        __syncthreads();
        if (s + 2 < 16) {
            int nbuf = buf + 2; if (nbuf >= NPIPE) nbuf -= NPIPE;
            load_stage(s + 2, nbuf);
        }

        const float* Asf = smf + buf * (STAGE_B / 4);
        const float* Bsf = Asf + (ASZ_B / 4);

        #pragma unroll
        for (int ks = 0; ks < 4; ks++) {
            int k = ks * 8;
            uint32_t a[2][4], b[8][2];
            #pragma unroll
            for (int mt = 0; mt < 2; mt++) {
                int r0 = warpM * 32 + mt * 16 + gr;
                float a0 = Asf[r0 * 36 + k + gc];
                float a1 = Asf[(r0 + 8) * 36 + k + gc];
                float a2 = Asf[r0 * 36 + k + gc + 4];
                float a3 = Asf[(r0 + 8) * 36 + k + gc + 4];
                if (CVT_A) {
                    a[mt][0] = f2tf32(a0); a[mt][1] = f2tf32(a1);
                    a[mt][2] = f2tf32(a2); a[mt][3] = f2tf32(a3);
                } else {
                    a[mt][0] = __float_as_uint(a0); a[mt][1] = __float_as_uint(a1);
                    a[mt][2] = __float_as_uint(a2); a[mt][3] = __float_as_uint(a3);
                }
            }
            #pragma unroll
            for (int nt = 0; nt < 8; nt++) {
                int cn = warpN * 64 + nt * 8 + gr;
                b[nt][0] = __float_as_uint(Bsf[(k + gc) * 136 + cn]);
                b[nt][1] = __float_as_uint(Bsf[(k + gc + 4) * 136 + cn]);
            }
            #pragma unroll
            for (int mt = 0; mt < 2; mt++)
                #pragma unroll
                for (int nt = 0; nt < 8; nt++) {
                    asm volatile(
                        "mma.sync.aligned.m16n8k8.row.col.f32.tf32.tf32.f32 "
                        "{%0,%1,%2,%3}, {%4,%5,%6,%7}, {%8,%9}, {%0,%1,%2,%3};"
                        : "+f"(acc[mt][nt][0]), "+f"(acc[mt][nt][1]),
                          "+f"(acc[mt][nt][2]), "+f"(acc[mt][nt][3])
                        : "r"(a[mt][0]), "r"(a[mt][1]), "r"(a[mt][2]), "r"(a[mt][3]),
                          "r"(b[nt][0]), "r"(b[nt][1]));
                }
        }
        buf++; if (buf >= NPIPE) buf -= NPIPE;
    }

    #pragma unroll
    for (int mt = 0; mt < 2; mt++) {
        int row = bm * 128 + warpM * 32 + mt * 16 + gr;
        #pragma unroll
        for (int nt = 0; nt < 8; nt++) {
            int col = bcol * 128 + warpN * 64 + nt * 8 + 2 * gc;
            float2 lo = make_float2(acc[mt][nt][0], acc[mt][nt][1]);
            float2 hi = make_float2(acc[mt][nt][2], acc[mt][nt][3]);
            *(float2*)(C + (size_t)row * Cc + col)       = lo;
            *(float2*)(C + (size_t)(row + 8) * Cc + col) = hi;
        }
    }
}

// ---------------------------------------------------------------------------
// GEMM path B: fp32 SIMT FFMA body (R3 sgemm, proven 43 TF/s).
// Runs on the FMA pipe, which is idle under the tensor body — assigned 25%
// of output tiles so both pipes work concurrently on co-resident blocks.
// Uses first ~17 KB of the (tensor-sized) dynamic smem allocation.
// ---------------------------------------------------------------------------
__device__ __forceinline__ void sgemm_body(
    const float* __restrict__ A, const float* __restrict__ Bw,
    float* __restrict__ C, int bm, int bcol)
{
    extern __shared__ char smem[];
    float (*As)[132] = (float (*)[132])smem;                       // [16][132]
    float (*Bs)[128] = (float (*)[128])(smem + 16 * 132 * 4);      // [16][128]

    int tid = threadIdx.x;
    int tx = tid & 15, ty = tid >> 4;

    float acc[8][8];
    #pragma unroll
    for (int i = 0; i < 8; i++)
        #pragma unroll
        for (int j = 0; j < 8; j++) acc[i][j] = 0.f;

    const float* Ab = A + (size_t)(bm * 128) * Cc;
    const float* Bp = Bw + bcol * 128;

    #pragma unroll 1
    for (int k0 = 0; k0 < Cc; k0 += 16) {
        #pragma unroll
        for (int i = 0; i < 2; i++) {
            int idx = tid + i * 256;
            int row = idx >> 2;
            int c4  = idx & 3;
            float4 v = *(const float4*)(Ab + (size_t)row * Cc + k0 + c4 * 4);
            As[c4*4+0][row] = v.x;
            As[c4*4+1][row] = v.y;
            As[c4*4+2][row] = v.z;
            As[c4*4+3][row] = v.w;
        }
        #pragma unroll
        for (int i = 0; i < 2; i++) {
            int idx = tid + i * 256;
            int row = idx >> 5;
            int c4  = idx & 31;
            *(float4*)(&Bs[row][c4*4]) =
                *(const float4*)(Bp + (size_t)(k0 + row) * Cc + c4 * 4);
        }
        __syncthreads();

        #pragma unroll
        for (int kk = 0; kk < 16; kk++) {
            float a[8], b[8];
            *(float4*)(a)     = *(const float4*)(&As[kk][ty*8]);
            *(float4*)(a + 4) = *(const float4*)(&As[kk][ty*8 + 4]);
            *(float4*)(b)     = *(const float4*)(&Bs[kk][tx*8]);
            *(float4*)(b + 4) = *(const float4*)(&Bs[kk][tx*8 + 4]);
            #pragma unroll
            for (int i = 0; i < 8; i++)
                #pragma unroll
                for (int j = 0; j < 8; j++)
                    acc[i][j] += a[i] * b[j];
        }
        __syncthreads();
    }

    float* Cb = C + (size_t)(bm * 128 + ty * 8) * Cc + bcol * 128 + tx * 8;
    #pragma unroll
    for (int i = 0; i < 8; i++) {
        *(float4*)(Cb + (size_t)i * Cc)     = *(float4*)(&acc[i][0]);
        *(float4*)(Cb + (size_t)i * Cc + 4) = *(float4*)(&acc[i][4]);
    }
}

// Fused QKV projection: grid (12, 256). bn>>2 selects Wq/Wk/Wv and Q/K/V out.
// 25% of tiles ((bm+bn)%4==3) take the FFMA path (fp32-exact on those cols).
__global__ __launch_bounds__(256, 2) void qkv_gemm_kernel(
    const float* __restrict__ X, const float* __restrict__ Wt,
    float* __restrict__ Qo, float* __restrict__ Ko, float* __restrict__ Vo)
{
    int bn = blockIdx.x;
    int bm = blockIdx.y;
    int z = bn >> 2, bc = bn & 3;
    const float* Bw = Wt + (size_t)z * Cc * Cc;
    float* C = (z == 0) ? Qo : (z == 1) ? Ko : Vo;
    if (((bm + bn) & 3) == 3)
        sgemm_body(X, Bw, C, bm, bc);
    else
        gemm_body<true>(X, Bw, C, bm, bc);
}

// Output projection: A pre-rounded tf32 (attn writes tf32), B pre-cvt'd.
__global__ __launch_bounds__(256, 2) void wo_gemm_kernel(
    const float* __restrict__ A, const float* __restrict__ Bw,
    float* __restrict__ C)
{
    int bn = blockIdx.x;
    int bm = blockIdx.y;
    if (((bm + bn) & 3) == 3)
        sgemm_body(A, Bw, C, bm, bn);
    else
        gemm_body<false>(A, Bw, C, bm, bn);
}

// ---------------------------------------------------------------------------
// Tensor-core flash attention with fused RoPE (unchanged from R10 — passing).
// ---------------------------------------------------------------------------
#define QS_OFF  0                 // 128 x 68
#define KS_OFF  8704              // 64 x 68
#define VS_OFF  13056             // 64 x 72
#define PS_OFF  17664             // 128 x 68
#define ATT_SMEM_F 26368
#define ATT_SMEM_B (ATT_SMEM_F*4) // 105472

#define MASKVAL (-3.0e38f)

__global__ __launch_bounds__(128) void attn_mma_kernel(
    const float* __restrict__ Q, const float* __restrict__ K,
    const float* __restrict__ V, float* __restrict__ O)
{
    extern __shared__ float sm[];
    int w = blockIdx.x, b = blockIdx.y, h = blockIdx.z;
    int tid = threadIdx.x;
    int lane = tid & 31;
    int wid = tid >> 5;
    int gr = lane >> 2;
    int gc = lane & 3;
    int base_p = w * Ww - 64;

    // Stage Q tile (128x64) with rope, scale 1/8, tf32.
    {
        const float* Qg = Q + ((size_t)(b * Tt + w * Ww)) * Cc + h * Dd;
        #pragma unroll
        for (int i = 0; i < 8; i++) {
            int idx = tid + i * 128;
            int r = idx >> 3, cg = idx & 7;
            int t = w * Ww + r;
            float4 q1 = *(const float4*)(Qg + (size_t)r * Cc + cg * 4);
            float4 q2 = *(const float4*)(Qg + (size_t)r * Cc + cg * 4 + 32);
            float4 cv = *(const float4*)(g_cos + t * 32 + cg * 4);
            float4 sv = *(const float4*)(g_sin + t * 32 + cg * 4);
            float* d1 = sm + QS_OFF + r * 68 + cg * 4;
            float* d2 = d1 + 32;
            d1[0] = f2tf32f((q1.x * cv.x - q2.x * sv.x) * 0.125f);
            d1[1] = f2tf32f((q1.y * cv.y - q2.y * sv.y) * 0.125f);
            d1[2] = f2tf32f((q1.z * cv.z - q2.z * sv.z) * 0.125f);
            d1[3] = f2tf32f((q1.w * cv.w - q2.w * sv.w) * 0.125f);
            d2[0] = f2tf32f((q2.x * cv.x + q1.x * sv.x) * 0.125f);
            d2[1] = f2tf32f((q2.y * cv.y + q1.y * sv.y) * 0.125f);
            d2[2] = f2tf32f((q2.z * cv.z + q1.z * sv.z) * 0.125f);
            d2[3] = f2tf32f((q2.w * cv.w + q1.w * sv.w) * 0.125f);
        }
    }

    float oacc[2][8][4];
    #pragma unroll
    for (int mt = 0; mt < 2; mt++)
        #pragma unroll
        for (int nt = 0; nt < 8; nt++)
            #pragma unroll
            for (int j = 0; j < 4; j++) oacc[mt][nt][j] = 0.f;
    float mrow[2][2], lrow[2][2];
    #pragma unroll
    for (int mt = 0; mt < 2; mt++) {
        mrow[mt][0] = -1e30f; mrow[mt][1] = -1e30f;
        lrow[mt][0] = 0.f;    lrow[mt][1] = 0.f;
    }

    #pragma unroll 1
    for (int kc = 0; kc < 4; kc++) {
        __syncthreads();

        int p0 = base_p + kc * 64;
        // Stage K chunk (64x64) with rope, tf32.
        #pragma unroll
        for (int i = 0; i < 4; i++) {
            int idx = tid + i * 128;
            int r = idx >> 3, cg = idx & 7;
            int p = p0 + r;
            float* d1 = sm + KS_OFF + r * 68 + cg * 4;
            float* d2 = d1 + 32;
            if (p >= 0 && p < Tt) {
                size_t off = ((size_t)(b * Tt + p)) * Cc + h * Dd + cg * 4;
                float4 k1 = *(const float4*)(K + off);
                float4 k2 = *(const float4*)(K + off + 32);
                float4 cv = *(const float4*)(g_cos + p * 32 + cg * 4);
                float4 sv = *(const float4*)(g_sin + p * 32 + cg * 4);
                d1[0] = f2tf32f(k1.x * cv.x - k2.x * sv.x);
                d1[1] = f2tf32f(k1.y * cv.y - k2.y * sv.y);
                d1[2] = f2tf32f(k1.z * cv.z - k2.z * sv.z);
                d1[3] = f2tf32f(k1.w * cv.w - k2.w * sv.w);
                d2[0] = f2tf32f(k2.x * cv.x + k1.x * sv.x);
                d2[1] = f2tf32f(k2.y * cv.y + k1.y * sv.y);
                d2[2] = f2tf32f(k2.z * cv.z + k1.z * sv.z);
                d2[3] = f2tf32f(k2.w * cv.w + k1.w * sv.w);
            } else {
                d1[0] = d1[1] = d1[2] = d1[3] = 0.f;
                d2[0] = d2[1] = d2[2] = d2[3] = 0.f;
            }
        }
        // Stage V chunk (64x64), tf32 (no rope).
        #pragma unroll
        for (int i = 0; i < 8; i++) {
            int idx = tid + i * 128;
            int r = idx >> 4, c4 = idx & 15;
            int p = p0 + r;
            float* vd = sm + VS_OFF + r * 72 + c4 * 4;
            if (p >= 0 && p < Tt) {
                size_t off = ((size_t)(b * Tt + p)) * Cc + h * Dd + c4 * 4;
                float4 vv = *(const float4*)(V + off);
                vd[0] = f2tf32f(vv.x); vd[1] = f2tf32f(vv.y);
                vd[2] = f2tf32f(vv.z); vd[3] = f2tf32f(vv.w);
            } else {
                vd[0] = vd[1] = vd[2] = vd[3] = 0.f;
            }
        }
        __syncthreads();

        // S = Qs @ Ks^T
        float sacc[2][8][4];
        #pragma unroll
        for (int mt = 0; mt < 2; mt++)
            #pragma unroll
            for (int nt = 0; nt < 8; nt++)
                #pragma unroll
                for (int j = 0; j < 4; j++) sacc[mt][nt][j] = 0.f;

        #pragma unroll
        for (int ks = 0; ks < 8; ks++) {
            int k0 = ks * 8;
            uint32_t a[2][4];
            #pragma unroll
            for (int mt = 0; mt < 2; mt++) {
                int r0 = wid * 32 + mt * 16 + gr;
                const float* qb = sm + QS_OFF + k0 + gc;
                a[mt][0] = __float_as_uint(qb[r0 * 68]);
                a[mt][1] = __float_as_uint(qb[(r0 + 8) * 68]);
                a[mt][2] = __float_as_uint(qb[r0 * 68 + 4]);
                a[mt][3] = __float_as_uint(qb[(r0 + 8) * 68 + 4]);
            }
            #pragma unroll
            for (int nt = 0; nt < 8; nt++) {
                uint32_t b0 = __float_as_uint(sm[KS_OFF + (nt * 8 + gr) * 68 + k0 + gc]);
                uint32_t b1 = __float_as_uint(sm[KS_OFF + (nt * 8 + gr) * 68 + k0 + gc + 4]);
                #pragma unroll
                for (int mt = 0; mt < 2; mt++)
                    asm volatile(
                        "mma.sync.aligned.m16n8k8.row.col.f32.tf32.tf32.f32 "
                        "{%0,%1,%2,%3}, {%4,%5,%6,%7}, {%8,%9}, {%0,%1,%2,%3};"
                        : "+f"(sacc[mt][nt][0]), "+f"(sacc[mt][nt][1]),
                          "+f"(sacc[mt][nt][2]), "+f"(sacc[mt][nt][3])
                        : "r"(a[mt][0]), "r"(a[mt][1]), "r"(a[mt][2]), "r"(a[mt][3]),
                          "r"(b0), "r"(b1));
            }
        }

        // Mask invalid key columns
        if (p0 < 0 || p0 + 64 > Tt) {
            #pragma unroll
            for (int nt = 0; nt < 8; nt++) {
                int q0 = p0 + nt * 8 + 2 * gc;
                int q1 = q0 + 1;
                bool v0 = (q0 >= 0) && (q0 < Tt);
                bool v1 = (q1 >= 0) && (q1 < Tt);
                #pragma unroll
                for (int mt = 0; mt < 2; mt++) {
                    if (!v0) { sacc[mt][nt][0] = MASKVAL; sacc[mt][nt][2] = MASKVAL; }
                    if (!v1) { sacc[mt][nt][1] = MASKVAL; sacc[mt][nt][3] = MASKVAL; }
                }
            }
        }

        // Online softmax + P store
        #pragma unroll
        for (int mt = 0; mt < 2; mt++) {
            float mx_lo = MASKVAL, mx_hi = MASKVAL;
            #pragma unroll
            for (int nt = 0; nt < 8; nt++) {
                mx_lo = fmaxf(mx_lo, fmaxf(sacc[mt][nt][0], sacc[mt][nt][1]));
                mx_hi = fmaxf(mx_hi, fmaxf(sacc[mt][nt][2], sacc[mt][nt][3]));
            }
            mx_lo = fmaxf(mx_lo, __shfl_xor_sync(0xffffffffu, mx_lo, 1));
            mx_lo = fmaxf(mx_lo, __shfl_xor_sync(0xffffffffu, mx_lo, 2));
            mx_hi = fmaxf(mx_hi, __shfl_xor_sync(0xffffffffu, mx_hi, 1));
            mx_hi = fmaxf(mx_hi, __shfl_xor_sync(0xffffffffu, mx_hi, 2));

            float mn_lo = fmaxf(mrow[mt][0], mx_lo);
            float mn_hi = fmaxf(mrow[mt][1], mx_hi);
            float sf_lo = __expf(mrow[mt][0] - mn_lo);
            float sf_hi = __expf(mrow[mt][1] - mn_hi);
            mrow[mt][0] = mn_lo; mrow[mt][1] = mn_hi;

            float sum_lo = 0.f, sum_hi = 0.f;
            int r_lo = wid * 32 + mt * 16 + gr;
            float* prow_lo = sm + PS_OFF + r_lo * 68;
            float* prow_hi = prow_lo + 8 * 68;
            #pragma unroll
            for (int nt = 0; nt < 8; nt++) {
                float p0e = __expf(sacc[mt][nt][0] - mn_lo);
                float p1e = __expf(sacc[mt][nt][1] - mn_lo);
                float p2e = __expf(sacc[mt][nt][2] - mn_hi);
                float p3e = __expf(sacc[mt][nt][3] - mn_hi);
                sum_lo += p0e + p1e;
                sum_hi += p2e + p3e;
                int c = nt * 8 + 2 * gc;
                prow_lo[c]     = f2tf32f(p0e);
                prow_lo[c + 1] = f2tf32f(p1e);
                prow_hi[c]     = f2tf32f(p2e);
                prow_hi[c + 1] = f2tf32f(p3e);
            }
            sum_lo += __shfl_xor_sync(0xffffffffu, sum_lo, 1);
            sum_lo += __shfl_xor_sync(0xffffffffu, sum_lo, 2);
            sum_hi += __shfl_xor_sync(0xffffffffu, sum_hi, 1);
            sum_hi += __shfl_xor_sync(0xffffffffu, sum_hi, 2);
            lrow[mt][0] = lrow[mt][0] * sf_lo + sum_lo;
            lrow[mt][1] = lrow[mt][1] * sf_hi + sum_hi;

            #pragma unroll
            for (int nt = 0; nt < 8; nt++) {
                oacc[mt][nt][0] *= sf_lo;
                oacc[mt][nt][1] *= sf_lo;
                oacc[mt][nt][2] *= sf_hi;
                oacc[mt][nt][3] *= sf_hi;
            }
        }
        __syncwarp();

        // O += P @ V
        #pragma unroll
        for (int ks = 0; ks < 8; ks++) {
            int k0 = ks * 8;
            uint32_t a[2][4];
            #pragma unroll
            for (int mt = 0; mt < 2; mt++) {
                int r0 = wid * 32 + mt * 16 + gr;
                const float* pb = sm + PS_OFF + k0 + gc;
                a[mt][0] = __float_as_uint(pb[r0 * 68]);
                a[mt][1] = __float_as_uint(pb[(r0 + 8) * 68]);
                a[mt][2] = __float_as_uint(pb[r0 * 68 + 4]);
                a[mt][3] = __float_as_uint(pb[(r0 + 8) * 68 + 4]);
            }
            #pragma unroll
            for (int nt = 0; nt < 8; nt++) {
                uint32_t b0 = __float_as_uint(sm[VS_OFF + (k0 + gc) * 72 + nt * 8 + gr]);
                uint32_t b1 = __float_as_uint(sm[VS_OFF + (k0 + gc + 4) * 72 + nt * 8 + gr]);
                #pragma unroll
                for (int mt = 0; mt < 2; mt++)
                    asm volatile(
                        "mma.sync.aligned.m16n8k8.row.col.f32.tf32.tf32.f32 "
                        "{%0,%1,%2,%3}, {%4,%5,%6,%7}, {%8,%9}, {%0,%1,%2,%3};"
                        : "+f"(oacc[mt][nt][0]), "+f"(oacc[mt][nt][1]),
                          "+f"(oacc[mt][nt][2]), "+f"(oacc[mt][nt][3])
                        : "r"(a[mt][0]), "r"(a[mt][1]), "r"(a[mt][2]), "r"(a[mt][3]),
                          "r"(b0), "r"(b1));
            }
        }
    }

    // Normalize and write output, tf32-rounded (feeds Wo GEMM directly).
    #pragma unroll
    for (int mt = 0; mt < 2; mt++) {
        float inv_lo = 1.f / lrow[mt][0];
        float inv_hi = 1.f / lrow[mt][1];
        int row = b * Tt + w * Ww + wid * 32 + mt * 16 + gr;
        #pragma unroll
        for (int nt = 0; nt < 8; nt++) {
            int col = h * Dd + nt * 8 + 2 * gc;
            float2 lo = make_float2(f2tf32f(oacc[mt][nt][0] * inv_lo),
                                    f2tf32f(oacc[mt][nt][1] * inv_lo));
            float2 hi = make_float2(f2tf32f(oacc[mt][nt][2] * inv_hi),
                                    f2tf32f(oacc[mt][nt][3] * inv_hi));
            *(float2*)(O + (size_t)row * Cc + col)       = lo;
            *(float2*)(O + (size_t)(row + 8) * Cc + col) = hi;
        }
    }
}

// ---------------------------------------------------------------------------
extern "C" void kernel_launch(void* const* d_in, const int* in_sizes, int n_in,
                              void* d_out, int out_size)
{
    const float* x  = (const float*)d_in[0];
    const float* Wq = (const float*)d_in[2];
    const float* Wk = (const float*)d_in[3];
    const float* Wv = (const float*)d_in[4];
    const float* Wo = (const float*)d_in[5];
    float* out = (float*)d_out;

    static float *Qp = nullptr, *Kp = nullptr, *Vp = nullptr, *Op = nullptr;
    static float *Wtp = nullptr;
    static bool init_done = false;
    if (!init_done) {
        cudaGetSymbolAddress((void**)&Qp, g_Q);
        cudaGetSymbolAddress((void**)&Kp, g_K);
        cudaGetSymbolAddress((void**)&Vp, g_V);
        cudaGetSymbolAddress((void**)&Op, g_O);
        cudaGetSymbolAddress((void**)&Wtp, g_Wt);
        cudaFuncSetAttribute(attn_mma_kernel,
                             cudaFuncAttributeMaxDynamicSharedMemorySize,
                             ATT_SMEM_B);
        cudaFuncSetAttribute(qkv_gemm_kernel,
                             cudaFuncAttributeMaxDynamicSharedMemorySize,
                             GSMEM);
        cudaFuncSetAttribute(wo_gemm_kernel,
                             cudaFuncAttributeMaxDynamicSharedMemorySize,
                             GSMEM);
        init_done = true;
    }

    // 0. Fused prep: RoPE tables + 4 weight tf32 conversions (one launch)
    prep_kernel<<<(PREP_TOT + 255) / 256, 256>>>(Wq, Wk, Wv, Wo, Wtp);

    // 1. Fused Q/K/V projection, dual-pipe (75% tensor / 25% FFMA tiles)
    qkv_gemm_kernel<<<dim3(12, NROWS / 128), 256, GSMEM>>>(x, Wtp, Qp, Kp, Vp);

    // 2. Windowed attention with fused RoPE; writes tf32-rounded output
    dim3 agrid(NWIN, Bb, Hh);
    attn_mma_kernel<<<agrid, 128, ATT_SMEM_B>>>(Qp, Kp, Vp, Op);

    // 3. Output projection, dual-pipe
    wo_gemm_kernel<<<dim3(Cc / 128, NROWS / 128), 256, GSMEM>>>(
        Op, Wtp + 3 * Cc * Cc, out);
}